// round 13
// baseline (speedup 1.0000x reference)
#include <cuda_runtime.h>

#define C1 1.125f
#define C2 (-1.0f/24.0f)

__device__ __forceinline__ float4 ld4(const float* p) {
    return *reinterpret_cast<const float4*>(p);
}
__device__ __forceinline__ void st4(float* p, float4 v) {
    *reinterpret_cast<float4*>(p) = v;
}
__device__ __forceinline__ float4 f4zero() { return make_float4(0.f,0.f,0.f,0.f); }

__device__ __forceinline__ float frcp(float x) {
    float r; asm("rcp.approx.f32 %0, %1;" : "=f"(r) : "f"(x)); return r;
}
__device__ __forceinline__ float4 frcp4(float4 v) {
    float4 r; r.x = frcp(v.x); r.y = frcp(v.y); r.z = frcp(v.z); r.w = frcp(v.w); return r;
}

// (C1*(a-b) + C2*(c-d)) * s
__device__ __forceinline__ float4 stencil4(float4 a, float4 b, float4 c, float4 d, float s) {
    float4 r;
    r.x = (C1 * (a.x - b.x) + C2 * (c.x - d.x)) * s;
    r.y = (C1 * (a.y - b.y) + C2 * (c.y - d.y)) * s;
    r.z = (C1 * (a.z - b.z) + C2 * (c.z - d.z)) * s;
    r.w = (C1 * (a.w - b.w) + C2 * (c.w - d.w)) * s;
    return r;
}
// update_E x-stencil: lanewise needs x-2..x+1
__device__ __forceinline__ float4 xderiv_E(float4 c, float4 p, float4 n, float s) {
    float4 r;
    r.x = (C1 * (c.x - p.w) + C2 * (c.y - p.z)) * s;
    r.y = (C1 * (c.y - c.x) + C2 * (c.z - p.w)) * s;
    r.z = (C1 * (c.z - c.y) + C2 * (c.w - c.x)) * s;
    r.w = (C1 * (c.w - c.z) + C2 * (n.x - c.y)) * s;
    return r;
}
// update_H x-stencil: lanewise needs x-1..x+2
__device__ __forceinline__ float4 xderiv_H(float4 c, float4 p, float4 n, float s) {
    float4 r;
    r.x = (C1 * (c.y - c.x) + C2 * (c.z - p.w)) * s;
    r.y = (C1 * (c.z - c.y) + C2 * (c.w - c.x)) * s;
    r.z = (C1 * (c.w - c.z) + C2 * (n.x - c.y)) * s;
    r.w = (C1 * (n.x - c.w) + C2 * (n.y - c.z)) * s;
    return r;
}

// each thread: 8 consecutive x floats (two float4 at +0 / +4), 1 y row
// ---------------- Kernel 1: update_E ----------------
__global__ void __launch_bounds__(128) upd_E(
    const float* __restrict__ ca, const float* __restrict__ cb,
    const float* __restrict__ Ey, const float* __restrict__ Hx,
    const float* __restrict__ Hz,
    const float* __restrict__ mHxz, const float* __restrict__ mHzx,
    const float* __restrict__ ky, const float* __restrict__ ay,
    const float* __restrict__ by,
    const float* __restrict__ kx, const float* __restrict__ ax,
    const float* __restrict__ bx,
    const float* __restrict__ prdy, const float* __restrict__ prdx,
    float* __restrict__ outEy, float* __restrict__ outmHxz,
    float* __restrict__ outmHzx,
    int NY, int NX)
{
    int x8 = (blockIdx.x * blockDim.x + threadIdx.x) * 8;
    int y  = blockIdx.y * blockDim.y + threadIdx.y;
    int b  = blockIdx.z;
    if (x8 >= NX || y >= NY) return;

    const float rdx = *prdx;
    const float rdy = *prdy;

    size_t plane = (size_t)NY * NX;
    size_t base  = (size_t)b * plane + (size_t)y * NX + x8;   // f4 "a" at +0, "b" at +4

    const bool xlo = (x8 >= 4);
    const bool xhi = (x8 + 8 < NX);
    const bool y1 = (y >= 1), y2 = (y >= 2), yp = (y + 1 < NY);

    // ---- x-derivative of Hz ----
    float4 ha = ld4(Hz + base);
    float4 hb = ld4(Hz + base + 4);
    float4 hp = xlo ? ld4(Hz + base - 4) : f4zero();
    float4 hn = xhi ? ld4(Hz + base + 8) : f4zero();
    float4 dHzdx_a = xderiv_E(ha, hp, hb, rdx);
    float4 dHzdx_b = xderiv_E(hb, ha, hn, rdx);

    // ---- y-derivative of Hx (rows y-2..y+1, both x-halves) ----
    float4 r0a  = ld4(Hx + base);
    float4 r0b  = ld4(Hx + base + 4);
    float4 rm1a = y1 ? ld4(Hx + base -   (size_t)NX)     : f4zero();
    float4 rm1b = y1 ? ld4(Hx + base -   (size_t)NX + 4) : f4zero();
    float4 rm2a = y2 ? ld4(Hx + base - 2*(size_t)NX)     : f4zero();
    float4 rm2b = y2 ? ld4(Hx + base - 2*(size_t)NX + 4) : f4zero();
    float4 rp1a = yp ? ld4(Hx + base +   (size_t)NX)     : f4zero();
    float4 rp1b = yp ? ld4(Hx + base +   (size_t)NX + 4) : f4zero();
    float4 dHxdz_a = stencil4(r0a, rm1a, rp1a, rm2a, rdy);
    float4 dHxdz_b = stencil4(r0b, rm1b, rp1b, rm2b, rdy);

    // ---- coefficients ----
    float4 bxa = ld4(bx + x8), bxb = ld4(bx + x8 + 4);
    float4 axa = ld4(ax + x8), axb = ld4(ax + x8 + 4);
    float4 rkxa = frcp4(ld4(kx + x8)), rkxb = frcp4(ld4(kx + x8 + 4));
    float  byv = by[y], ayv = ay[y];
    float  rky = frcp(ky[y]);

    size_t cell = (size_t)y * NX + x8;

    // ---- half a ----
    {
        float4 mzx = ld4(mHzx + base);
        mzx.x = bxa.x * mzx.x + axa.x * dHzdx_a.x;
        mzx.y = bxa.y * mzx.y + axa.y * dHzdx_a.y;
        mzx.z = bxa.z * mzx.z + axa.z * dHzdx_a.z;
        mzx.w = bxa.w * mzx.w + axa.w * dHzdx_a.w;

        float4 mxz = ld4(mHxz + base);
        mxz.x = byv * mxz.x + ayv * dHxdz_a.x;
        mxz.y = byv * mxz.y + ayv * dHxdz_a.y;
        mxz.z = byv * mxz.z + ayv * dHxdz_a.z;
        mxz.w = byv * mxz.w + ayv * dHxdz_a.w;

        float4 ca4 = ld4(ca + cell);
        float4 cb4 = ld4(cb + cell);
        float4 ey  = ld4(Ey + base);
        ey.x = ca4.x * ey.x + cb4.x * ((dHzdx_a.x * rkxa.x + mzx.x) - (dHxdz_a.x * rky + mxz.x));
        ey.y = ca4.y * ey.y + cb4.y * ((dHzdx_a.y * rkxa.y + mzx.y) - (dHxdz_a.y * rky + mxz.y));
        ey.z = ca4.z * ey.z + cb4.z * ((dHzdx_a.z * rkxa.z + mzx.z) - (dHxdz_a.z * rky + mxz.z));
        ey.w = ca4.w * ey.w + cb4.w * ((dHzdx_a.w * rkxa.w + mzx.w) - (dHxdz_a.w * rky + mxz.w));

        st4(outEy   + base, ey);
        st4(outmHzx + base, mzx);
        st4(outmHxz + base, mxz);
    }
    // ---- half b ----
    {
        float4 mzx = ld4(mHzx + base + 4);
        mzx.x = bxb.x * mzx.x + axb.x * dHzdx_b.x;
        mzx.y = bxb.y * mzx.y + axb.y * dHzdx_b.y;
        mzx.z = bxb.z * mzx.z + axb.z * dHzdx_b.z;
        mzx.w = bxb.w * mzx.w + axb.w * dHzdx_b.w;

        float4 mxz = ld4(mHxz + base + 4);
        mxz.x = byv * mxz.x + ayv * dHxdz_b.x;
        mxz.y = byv * mxz.y + ayv * dHxdz_b.y;
        mxz.z = byv * mxz.z + ayv * dHxdz_b.z;
        mxz.w = byv * mxz.w + ayv * dHxdz_b.w;

        float4 ca4 = ld4(ca + cell + 4);
        float4 cb4 = ld4(cb + cell + 4);
        float4 ey  = ld4(Ey + base + 4);
        ey.x = ca4.x * ey.x + cb4.x * ((dHzdx_b.x * rkxb.x + mzx.x) - (dHxdz_b.x * rky + mxz.x));
        ey.y = ca4.y * ey.y + cb4.y * ((dHzdx_b.y * rkxb.y + mzx.y) - (dHxdz_b.y * rky + mxz.y));
        ey.z = ca4.z * ey.z + cb4.z * ((dHzdx_b.z * rkxb.z + mzx.z) - (dHxdz_b.z * rky + mxz.z));
        ey.w = ca4.w * ey.w + cb4.w * ((dHzdx_b.w * rkxb.w + mzx.w) - (dHxdz_b.w * rky + mxz.w));

        st4(outEy   + base + 4, ey);
        st4(outmHzx + base + 4, mzx);
        st4(outmHxz + base + 4, mxz);
    }
}

// ---------------- Kernel 2: update_H ----------------
__global__ void __launch_bounds__(128) upd_H(
    const float* __restrict__ cq,
    const float* __restrict__ EyNew,
    const float* __restrict__ Hx, const float* __restrict__ Hz,
    const float* __restrict__ mEyx, const float* __restrict__ mEyz,
    const float* __restrict__ kyh, const float* __restrict__ ayh,
    const float* __restrict__ byh,
    const float* __restrict__ kxh, const float* __restrict__ axh,
    const float* __restrict__ bxh,
    const float* __restrict__ prdy, const float* __restrict__ prdx,
    float* __restrict__ outHx, float* __restrict__ outHz,
    float* __restrict__ outmEyx, float* __restrict__ outmEyz,
    int NY, int NX)
{
    int x8 = (blockIdx.x * blockDim.x + threadIdx.x) * 8;
    int y  = blockIdx.y * blockDim.y + threadIdx.y;
    int b  = blockIdx.z;
    if (x8 >= NX || y >= NY) return;

    const float rdx = *prdx;
    const float rdy = *prdy;

    size_t plane = (size_t)NY * NX;
    size_t base  = (size_t)b * plane + (size_t)y * NX + x8;

    const bool xlo = (x8 >= 4);
    const bool xhi = (x8 + 8 < NX);
    const bool ym1 = (y >= 1), yp1 = (y + 1 < NY), yp2 = (y + 2 < NY);

    // ---- EyNew center row halves + x halos ----
    float4 ea = ld4(EyNew + base);
    float4 eb = ld4(EyNew + base + 4);
    float4 ep = xlo ? ld4(EyNew + base - 4) : f4zero();
    float4 en = xhi ? ld4(EyNew + base + 8) : f4zero();
    float4 dEydx_a = xderiv_H(ea, ep, eb, rdx);
    float4 dEydx_b = xderiv_H(eb, ea, en, rdx);

    // ---- EyNew y rows (y-1, y+1, y+2) both halves ----
    float4 rm1a = ym1 ? ld4(EyNew + base -   (size_t)NX)     : f4zero();
    float4 rm1b = ym1 ? ld4(EyNew + base -   (size_t)NX + 4) : f4zero();
    float4 rp1a = yp1 ? ld4(EyNew + base +   (size_t)NX)     : f4zero();
    float4 rp1b = yp1 ? ld4(EyNew + base +   (size_t)NX + 4) : f4zero();
    float4 rp2a = yp2 ? ld4(EyNew + base + 2*(size_t)NX)     : f4zero();
    float4 rp2b = yp2 ? ld4(EyNew + base + 2*(size_t)NX + 4) : f4zero();
    float4 dEydz_a = stencil4(rp1a, ea, rp2a, rm1a, rdy);
    float4 dEydz_b = stencil4(rp1b, eb, rp2b, rm1b, rdy);

    // ---- coefficients ----
    float4 bxha = ld4(bxh + x8), bxhb = ld4(bxh + x8 + 4);
    float4 axha = ld4(axh + x8), axhb = ld4(axh + x8 + 4);
    float4 rkxha = frcp4(ld4(kxh + x8)), rkxhb = frcp4(ld4(kxh + x8 + 4));
    float  byhv = byh[y], ayhv = ayh[y];
    float  rkyh = frcp(kyh[y]);

    size_t cell = (size_t)y * NX + x8;

    // ---- half a ----
    {
        float4 mez = ld4(mEyz + base);
        mez.x = byhv * mez.x + ayhv * dEydz_a.x;
        mez.y = byhv * mez.y + ayhv * dEydz_a.y;
        mez.z = byhv * mez.z + ayhv * dEydz_a.z;
        mez.w = byhv * mez.w + ayhv * dEydz_a.w;

        float4 mex = ld4(mEyx + base);
        mex.x = bxha.x * mex.x + axha.x * dEydx_a.x;
        mex.y = bxha.y * mex.y + axha.y * dEydx_a.y;
        mex.z = bxha.z * mex.z + axha.z * dEydx_a.z;
        mex.w = bxha.w * mex.w + axha.w * dEydx_a.w;

        float4 cq4 = ld4(cq + cell);
        float4 hx = ld4(Hx + base);
        hx.x = hx.x - cq4.x * (dEydz_a.x * rkyh + mez.x);
        hx.y = hx.y - cq4.y * (dEydz_a.y * rkyh + mez.y);
        hx.z = hx.z - cq4.z * (dEydz_a.z * rkyh + mez.z);
        hx.w = hx.w - cq4.w * (dEydz_a.w * rkyh + mez.w);

        float4 hz = ld4(Hz + base);
        hz.x = hz.x + cq4.x * (dEydx_a.x * rkxha.x + mex.x);
        hz.y = hz.y + cq4.y * (dEydx_a.y * rkxha.y + mex.y);
        hz.z = hz.z + cq4.z * (dEydx_a.z * rkxha.z + mex.z);
        hz.w = hz.w + cq4.w * (dEydx_a.w * rkxha.w + mex.w);

        st4(outHx   + base, hx);
        st4(outHz   + base, hz);
        st4(outmEyz + base, mez);
        st4(outmEyx + base, mex);
    }
    // ---- half b ----
    {
        float4 mez = ld4(mEyz + base + 4);
        mez.x = byhv * mez.x + ayhv * dEydz_b.x;
        mez.y = byhv * mez.y + ayhv * dEydz_b.y;
        mez.z = byhv * mez.z + ayhv * dEydz_b.z;
        mez.w = byhv * mez.w + ayhv * dEydz_b.w;

        float4 mex = ld4(mEyx + base + 4);
        mex.x = bxhb.x * mex.x + axhb.x * dEydx_b.x;
        mex.y = bxhb.y * mex.y + axhb.y * dEydx_b.y;
        mex.z = bxhb.z * mex.z + axhb.z * dEydx_b.z;
        mex.w = bxhb.w * mex.w + axhb.w * dEydx_b.w;

        float4 cq4 = ld4(cq + cell + 4);
        float4 hx = ld4(Hx + base + 4);
        hx.x = hx.x - cq4.x * (dEydz_b.x * rkyh + mez.x);
        hx.y = hx.y - cq4.y * (dEydz_b.y * rkyh + mez.y);
        hx.z = hx.z - cq4.z * (dEydz_b.z * rkyh + mez.z);
        hx.w = hx.w - cq4.w * (dEydz_b.w * rkyh + mez.w);

        float4 hz = ld4(Hz + base + 4);
        hz.x = hz.x + cq4.x * (dEydx_b.x * rkxhb.x + mex.x);
        hz.y = hz.y + cq4.y * (dEydx_b.y * rkxhb.y + mex.y);
        hz.z = hz.z + cq4.z * (dEydx_b.z * rkxhb.z + mex.z);
        hz.w = hz.w + cq4.w * (dEydx_b.w * rkxhb.w + mex.w);

        st4(outHx   + base + 4, hx);
        st4(outHz   + base + 4, hz);
        st4(outmEyz + base + 4, mez);
        st4(outmEyx + base + 4, mex);
    }
}

extern "C" void kernel_launch(void* const* d_in, const int* in_sizes, int n_in,
                              void* d_out, int out_size)
{
    const float* ca    = (const float*)d_in[0];
    const float* cb    = (const float*)d_in[1];
    const float* cq    = (const float*)d_in[2];
    const float* Ey    = (const float*)d_in[3];
    const float* Hx    = (const float*)d_in[4];
    const float* Hz    = (const float*)d_in[5];
    const float* mHxz  = (const float*)d_in[6];
    const float* mHzx  = (const float*)d_in[7];
    const float* mEyx  = (const float*)d_in[8];
    const float* mEyz  = (const float*)d_in[9];
    const float* ky    = (const float*)d_in[10];
    const float* kyh   = (const float*)d_in[11];
    const float* ay    = (const float*)d_in[12];
    const float* ayh   = (const float*)d_in[13];
    const float* by    = (const float*)d_in[14];
    const float* byh   = (const float*)d_in[15];
    const float* kx    = (const float*)d_in[16];
    const float* kxh   = (const float*)d_in[17];
    const float* ax    = (const float*)d_in[18];
    const float* axh   = (const float*)d_in[19];
    const float* bx    = (const float*)d_in[20];
    const float* bxh   = (const float*)d_in[21];
    const float* prdy  = (const float*)d_in[22];
    const float* prdx  = (const float*)d_in[23];

    int NY = in_sizes[10];
    int NX = in_sizes[16];
    int B  = in_sizes[3] / (NY * NX);

    size_t plane = (size_t)NY * NX;
    size_t field = (size_t)B * plane;

    float* out = (float*)d_out;
    float* oEy   = out + 0 * field;
    float* oHx   = out + 1 * field;
    float* oHz   = out + 2 * field;
    float* omHxz = out + 3 * field;
    float* omHzx = out + 4 * field;
    float* omEyx = out + 5 * field;
    float* omEyz = out + 6 * field;

    // each thread: 8 consecutive x floats, 1 y row
    dim3 block(32, 4, 1);
    int nx8 = NX / 8;                        // 256
    dim3 grid((nx8 + 31) / 32, (NY + 3) / 4, B);

    upd_E<<<grid, block>>>(ca, cb, Ey, Hx, Hz, mHxz, mHzx,
                           ky, ay, by, kx, ax, bx, prdy, prdx,
                           oEy, omHxz, omHzx, NY, NX);

    upd_H<<<grid, block>>>(cq, oEy, Hx, Hz, mEyx, mEyz,
                           kyh, ayh, byh, kxh, axh, bxh, prdy, prdx,
                           oHx, oHz, omEyx, omEyz, NY, NX);
}

// round 14
// speedup vs baseline: 1.0035x; 1.0035x over previous
#include <cuda_runtime.h>

#define C1 1.125f
#define C2 (-1.0f/24.0f)

__device__ __forceinline__ float4 ld4(const float* p) {
    return *reinterpret_cast<const float4*>(p);
}
__device__ __forceinline__ void st4(float* p, float4 v) {
    *reinterpret_cast<float4*>(p) = v;
}
__device__ __forceinline__ float4 f4zero() { return make_float4(0.f,0.f,0.f,0.f); }

__device__ __forceinline__ float frcp(float x) {
    float r; asm("rcp.approx.f32 %0, %1;" : "=f"(r) : "f"(x)); return r;
}
__device__ __forceinline__ float4 frcp4(float4 v) {
    float4 r; r.x = frcp(v.x); r.y = frcp(v.y); r.z = frcp(v.z); r.w = frcp(v.w); return r;
}

// (C1*(a-b) + C2*(c-d)) * s
__device__ __forceinline__ float4 stencil4(float4 a, float4 b, float4 c, float4 d, float s) {
    float4 r;
    r.x = (C1 * (a.x - b.x) + C2 * (c.x - d.x)) * s;
    r.y = (C1 * (a.y - b.y) + C2 * (c.y - d.y)) * s;
    r.z = (C1 * (a.z - b.z) + C2 * (c.z - d.z)) * s;
    r.w = (C1 * (a.w - b.w) + C2 * (c.w - d.w)) * s;
    return r;
}
// update_E x-stencil: lanewise needs x-2..x+1
__device__ __forceinline__ float4 xderiv_E(float4 c, float4 p, float4 n, float s) {
    float4 r;
    r.x = (C1 * (c.x - p.w) + C2 * (c.y - p.z)) * s;
    r.y = (C1 * (c.y - c.x) + C2 * (c.z - p.w)) * s;
    r.z = (C1 * (c.z - c.y) + C2 * (c.w - c.x)) * s;
    r.w = (C1 * (c.w - c.z) + C2 * (n.x - c.y)) * s;
    return r;
}
// update_H x-stencil: lanewise needs x-1..x+2
__device__ __forceinline__ float4 xderiv_H(float4 c, float4 p, float4 n, float s) {
    float4 r;
    r.x = (C1 * (c.y - c.x) + C2 * (c.z - p.w)) * s;
    r.y = (C1 * (c.z - c.y) + C2 * (c.w - c.x)) * s;
    r.z = (C1 * (c.w - c.z) + C2 * (n.x - c.y)) * s;
    r.w = (C1 * (n.x - c.w) + C2 * (n.y - c.z)) * s;
    return r;
}

// ---------------- Kernel 1: update_E (x4 vector, 2 y-rows/thread) ----------------
__global__ void __launch_bounds__(256) upd_E(
    const float* __restrict__ ca, const float* __restrict__ cb,
    const float* __restrict__ Ey, const float* __restrict__ Hx,
    const float* __restrict__ Hz,
    const float* __restrict__ mHxz, const float* __restrict__ mHzx,
    const float* __restrict__ ky, const float* __restrict__ ay,
    const float* __restrict__ by,
    const float* __restrict__ kx, const float* __restrict__ ax,
    const float* __restrict__ bx,
    const float* __restrict__ prdy, const float* __restrict__ prdx,
    float* __restrict__ outEy, float* __restrict__ outmHxz,
    float* __restrict__ outmHzx,
    int NY, int NX)
{
    int x4 = (blockIdx.x * blockDim.x + threadIdx.x) * 4;
    int y0 = (blockIdx.y * blockDim.y + threadIdx.y) * 2;
    int b  = blockIdx.z;
    if (x4 >= NX || y0 >= NY) return;
    int y1 = y0 + 1;                         // NY even -> y1 < NY

    const float rdx = *prdx;
    const float rdy = *prdy;

    size_t plane = (size_t)NY * NX;
    size_t base0 = (size_t)b * plane + (size_t)y0 * NX + x4;
    size_t base1 = base0 + NX;

    // ---- x-derivative of Hz for both rows ----
    float4 c0 = ld4(Hz + base0);
    float4 c1 = ld4(Hz + base1);
    float4 p0 = (x4 >= 4)     ? ld4(Hz + base0 - 4) : f4zero();
    float4 p1 = (x4 >= 4)     ? ld4(Hz + base1 - 4) : f4zero();
    float4 n0 = (x4 + 4 < NX) ? ld4(Hz + base0 + 4) : f4zero();
    float4 n1 = (x4 + 4 < NX) ? ld4(Hz + base1 + 4) : f4zero();
    float4 dHzdx0 = xderiv_E(c0, p0, n0, rdx);
    float4 dHzdx1 = xderiv_E(c1, p1, n1, rdx);

    // ---- y-derivative of Hx: rows y0-2 .. y0+2 (5 loads for 2 rows) ----
    float4 h0 = (y0 >= 2)     ? ld4(Hx + base0 - 2*(size_t)NX) : f4zero();
    float4 h1 = (y0 >= 1)     ? ld4(Hx + base0 - (size_t)NX)   : f4zero();
    float4 h2 = ld4(Hx + base0);
    float4 h3 = ld4(Hx + base1);
    float4 h4 = (y0 + 2 < NY) ? ld4(Hx + base0 + 2*(size_t)NX) : f4zero();
    float4 dHxdz0 = stencil4(h2, h1, h3, h0, rdy);
    float4 dHxdz1 = stencil4(h3, h2, h4, h1, rdy);

    // ---- x coefficients (shared by both rows) ----
    float4 bx4  = ld4(bx + x4);
    float4 ax4  = ld4(ax + x4);
    float4 rkx4 = frcp4(ld4(kx + x4));
    float by0 = by[y0], ay0 = ay[y0], rky0 = frcp(ky[y0]);
    float by1 = by[y1], ay1 = ay[y1], rky1 = frcp(ky[y1]);

    // ---- row y0 ----
    {
        float4 mzx = ld4(mHzx + base0);
        mzx.x = bx4.x * mzx.x + ax4.x * dHzdx0.x;
        mzx.y = bx4.y * mzx.y + ax4.y * dHzdx0.y;
        mzx.z = bx4.z * mzx.z + ax4.z * dHzdx0.z;
        mzx.w = bx4.w * mzx.w + ax4.w * dHzdx0.w;

        float4 mxz = ld4(mHxz + base0);
        mxz.x = by0 * mxz.x + ay0 * dHxdz0.x;
        mxz.y = by0 * mxz.y + ay0 * dHxdz0.y;
        mxz.z = by0 * mxz.z + ay0 * dHxdz0.z;
        mxz.w = by0 * mxz.w + ay0 * dHxdz0.w;

        size_t cidx = (size_t)y0 * NX + x4;
        float4 ca4 = ld4(ca + cidx);
        float4 cb4 = ld4(cb + cidx);
        float4 ey  = ld4(Ey + base0);

        ey.x = ca4.x * ey.x + cb4.x * ((dHzdx0.x * rkx4.x + mzx.x) - (dHxdz0.x * rky0 + mxz.x));
        ey.y = ca4.y * ey.y + cb4.y * ((dHzdx0.y * rkx4.y + mzx.y) - (dHxdz0.y * rky0 + mxz.y));
        ey.z = ca4.z * ey.z + cb4.z * ((dHzdx0.z * rkx4.z + mzx.z) - (dHxdz0.z * rky0 + mxz.z));
        ey.w = ca4.w * ey.w + cb4.w * ((dHzdx0.w * rkx4.w + mzx.w) - (dHxdz0.w * rky0 + mxz.w));

        st4(outEy   + base0, ey);
        st4(outmHzx + base0, mzx);
        st4(outmHxz + base0, mxz);
    }
    // ---- row y1 ----
    {
        float4 mzx = ld4(mHzx + base1);
        mzx.x = bx4.x * mzx.x + ax4.x * dHzdx1.x;
        mzx.y = bx4.y * mzx.y + ax4.y * dHzdx1.y;
        mzx.z = bx4.z * mzx.z + ax4.z * dHzdx1.z;
        mzx.w = bx4.w * mzx.w + ax4.w * dHzdx1.w;

        float4 mxz = ld4(mHxz + base1);
        mxz.x = by1 * mxz.x + ay1 * dHxdz1.x;
        mxz.y = by1 * mxz.y + ay1 * dHxdz1.y;
        mxz.z = by1 * mxz.z + ay1 * dHxdz1.z;
        mxz.w = by1 * mxz.w + ay1 * dHxdz1.w;

        size_t cidx = (size_t)y1 * NX + x4;
        float4 ca4 = ld4(ca + cidx);
        float4 cb4 = ld4(cb + cidx);
        float4 ey  = ld4(Ey + base1);

        ey.x = ca4.x * ey.x + cb4.x * ((dHzdx1.x * rkx4.x + mzx.x) - (dHxdz1.x * rky1 + mxz.x));
        ey.y = ca4.y * ey.y + cb4.y * ((dHzdx1.y * rkx4.y + mzx.y) - (dHxdz1.y * rky1 + mxz.y));
        ey.z = ca4.z * ey.z + cb4.z * ((dHzdx1.z * rkx4.z + mzx.z) - (dHxdz1.z * rky1 + mxz.z));
        ey.w = ca4.w * ey.w + cb4.w * ((dHzdx1.w * rkx4.w + mzx.w) - (dHxdz1.w * rky1 + mxz.w));

        st4(outEy   + base1, ey);
        st4(outmHzx + base1, mzx);
        st4(outmHxz + base1, mxz);
    }
}

// ---------------- Kernel 2: update_H (x4 vector, 2 y-rows/thread) ----------------
__global__ void __launch_bounds__(256) upd_H(
    const float* __restrict__ cq,
    const float* __restrict__ EyNew,
    const float* __restrict__ Hx, const float* __restrict__ Hz,
    const float* __restrict__ mEyx, const float* __restrict__ mEyz,
    const float* __restrict__ kyh, const float* __restrict__ ayh,
    const float* __restrict__ byh,
    const float* __restrict__ kxh, const float* __restrict__ axh,
    const float* __restrict__ bxh,
    const float* __restrict__ prdy, const float* __restrict__ prdx,
    float* __restrict__ outHx, float* __restrict__ outHz,
    float* __restrict__ outmEyx, float* __restrict__ outmEyz,
    int NY, int NX)
{
    int x4 = (blockIdx.x * blockDim.x + threadIdx.x) * 4;
    int y0 = (blockIdx.y * blockDim.y + threadIdx.y) * 2;
    int b  = blockIdx.z;
    if (x4 >= NX || y0 >= NY) return;
    int y1 = y0 + 1;

    const float rdx = *prdx;
    const float rdy = *prdy;

    size_t plane = (size_t)NY * NX;
    size_t base0 = (size_t)b * plane + (size_t)y0 * NX + x4;
    size_t base1 = base0 + NX;

    // ---- EyNew rows: y0-1 .. y0+3 ----
    float4 e0 = (y0 >= 1)     ? ld4(EyNew + base0 - (size_t)NX)   : f4zero();
    float4 e1 = ld4(EyNew + base0);
    float4 e2 = ld4(EyNew + base1);
    float4 e3 = (y0 + 2 < NY) ? ld4(EyNew + base0 + 2*(size_t)NX) : f4zero();
    float4 e4 = (y0 + 3 < NY) ? ld4(EyNew + base0 + 3*(size_t)NX) : f4zero();

    // x-halos for both center rows
    float4 p0 = (x4 >= 4)     ? ld4(EyNew + base0 - 4) : f4zero();
    float4 p1 = (x4 >= 4)     ? ld4(EyNew + base1 - 4) : f4zero();
    float4 n0 = (x4 + 4 < NX) ? ld4(EyNew + base0 + 4) : f4zero();
    float4 n1 = (x4 + 4 < NX) ? ld4(EyNew + base1 + 4) : f4zero();

    float4 dEydx0 = xderiv_H(e1, p0, n0, rdx);
    float4 dEydx1 = xderiv_H(e2, p1, n1, rdx);
    float4 dEydz0 = stencil4(e2, e1, e3, e0, rdy);
    float4 dEydz1 = stencil4(e3, e2, e4, e1, rdy);

    // ---- x coefficients (shared) ----
    float4 bxh4  = ld4(bxh + x4);
    float4 axh4  = ld4(axh + x4);
    float4 rkxh4 = frcp4(ld4(kxh + x4));
    float byh0 = byh[y0], ayh0 = ayh[y0], rkyh0 = frcp(kyh[y0]);
    float byh1 = byh[y1], ayh1 = ayh[y1], rkyh1 = frcp(kyh[y1]);

    // ---- row y0 ----
    {
        float4 mez = ld4(mEyz + base0);
        mez.x = byh0 * mez.x + ayh0 * dEydz0.x;
        mez.y = byh0 * mez.y + ayh0 * dEydz0.y;
        mez.z = byh0 * mez.z + ayh0 * dEydz0.z;
        mez.w = byh0 * mez.w + ayh0 * dEydz0.w;

        float4 mex = ld4(mEyx + base0);
        mex.x = bxh4.x * mex.x + axh4.x * dEydx0.x;
        mex.y = bxh4.y * mex.y + axh4.y * dEydx0.y;
        mex.z = bxh4.z * mex.z + axh4.z * dEydx0.z;
        mex.w = bxh4.w * mex.w + axh4.w * dEydx0.w;

        size_t cidx = (size_t)y0 * NX + x4;
        float4 cq4 = ld4(cq + cidx);

        float4 hx = ld4(Hx + base0);
        hx.x = hx.x - cq4.x * (dEydz0.x * rkyh0 + mez.x);
        hx.y = hx.y - cq4.y * (dEydz0.y * rkyh0 + mez.y);
        hx.z = hx.z - cq4.z * (dEydz0.z * rkyh0 + mez.z);
        hx.w = hx.w - cq4.w * (dEydz0.w * rkyh0 + mez.w);

        float4 hz = ld4(Hz + base0);
        hz.x = hz.x + cq4.x * (dEydx0.x * rkxh4.x + mex.x);
        hz.y = hz.y + cq4.y * (dEydx0.y * rkxh4.y + mex.y);
        hz.z = hz.z + cq4.z * (dEydx0.z * rkxh4.z + mex.z);
        hz.w = hz.w + cq4.w * (dEydx0.w * rkxh4.w + mex.w);

        st4(outHx   + base0, hx);
        st4(outHz   + base0, hz);
        st4(outmEyz + base0, mez);
        st4(outmEyx + base0, mex);
    }
    // ---- row y1 ----
    {
        float4 mez = ld4(mEyz + base1);
        mez.x = byh1 * mez.x + ayh1 * dEydz1.x;
        mez.y = byh1 * mez.y + ayh1 * dEydz1.y;
        mez.z = byh1 * mez.z + ayh1 * dEydz1.z;
        mez.w = byh1 * mez.w + ayh1 * dEydz1.w;

        float4 mex = ld4(mEyx + base1);
        mex.x = bxh4.x * mex.x + axh4.x * dEydx1.x;
        mex.y = bxh4.y * mex.y + axh4.y * dEydx1.y;
        mex.z = bxh4.z * mex.z + axh4.z * dEydx1.z;
        mex.w = bxh4.w * mex.w + axh4.w * dEydx1.w;

        size_t cidx = (size_t)y1 * NX + x4;
        float4 cq4 = ld4(cq + cidx);

        float4 hx = ld4(Hx + base1);
        hx.x = hx.x - cq4.x * (dEydz1.x * rkyh1 + mez.x);
        hx.y = hx.y - cq4.y * (dEydz1.y * rkyh1 + mez.y);
        hx.z = hx.z - cq4.z * (dEydz1.z * rkyh1 + mez.z);
        hx.w = hx.w - cq4.w * (dEydz1.w * rkyh1 + mez.w);

        float4 hz = ld4(Hz + base1);
        hz.x = hz.x + cq4.x * (dEydx1.x * rkxh4.x + mex.x);
        hz.y = hz.y + cq4.y * (dEydx1.y * rkxh4.y + mex.y);
        hz.z = hz.z + cq4.z * (dEydx1.z * rkxh4.z + mex.z);
        hz.w = hz.w + cq4.w * (dEydx1.w * rkxh4.w + mex.w);

        st4(outHx   + base1, hx);
        st4(outHz   + base1, hz);
        st4(outmEyz + base1, mez);
        st4(outmEyx + base1, mex);
    }
}

extern "C" void kernel_launch(void* const* d_in, const int* in_sizes, int n_in,
                              void* d_out, int out_size)
{
    const float* ca    = (const float*)d_in[0];
    const float* cb    = (const float*)d_in[1];
    const float* cq    = (const float*)d_in[2];
    const float* Ey    = (const float*)d_in[3];
    const float* Hx    = (const float*)d_in[4];
    const float* Hz    = (const float*)d_in[5];
    const float* mHxz  = (const float*)d_in[6];
    const float* mHzx  = (const float*)d_in[7];
    const float* mEyx  = (const float*)d_in[8];
    const float* mEyz  = (const float*)d_in[9];
    const float* ky    = (const float*)d_in[10];
    const float* kyh   = (const float*)d_in[11];
    const float* ay    = (const float*)d_in[12];
    const float* ayh   = (const float*)d_in[13];
    const float* by    = (const float*)d_in[14];
    const float* byh   = (const float*)d_in[15];
    const float* kx    = (const float*)d_in[16];
    const float* kxh   = (const float*)d_in[17];
    const float* ax    = (const float*)d_in[18];
    const float* axh   = (const float*)d_in[19];
    const float* bx    = (const float*)d_in[20];
    const float* bxh   = (const float*)d_in[21];
    const float* prdy  = (const float*)d_in[22];
    const float* prdx  = (const float*)d_in[23];

    int NY = in_sizes[10];
    int NX = in_sizes[16];
    int B  = in_sizes[3] / (NY * NX);

    size_t plane = (size_t)NY * NX;
    size_t field = (size_t)B * plane;

    float* out = (float*)d_out;
    float* oEy   = out + 0 * field;
    float* oHx   = out + 1 * field;
    float* oHz   = out + 2 * field;
    float* omHxz = out + 3 * field;
    float* omHzx = out + 4 * field;
    float* omEyx = out + 5 * field;
    float* omEyz = out + 6 * field;

    // each thread: 4 x-elements x 2 y-rows; block covers 128 x-floats x 16 y-rows
    dim3 block(32, 8, 1);
    int nx4 = NX / 4;                       // 512
    int ny2 = (NY + 1) / 2;                 // 1024
    dim3 grid((nx4 + 31) / 32, (ny2 + 7) / 8, B);

    upd_E<<<grid, block>>>(ca, cb, Ey, Hx, Hz, mHxz, mHzx,
                           ky, ay, by, kx, ax, bx, prdy, prdx,
                           oEy, omHxz, omHzx, NY, NX);

    upd_H<<<grid, block>>>(cq, oEy, Hx, Hz, mEyx, mEyz,
                           kyh, ayh, byh, kxh, axh, bxh, prdy, prdx,
                           oHx, oHz, omEyx, omEyz, NY, NX);
}

// round 15
// speedup vs baseline: 1.0052x; 1.0017x over previous
#include <cuda_runtime.h>

#define C1 1.125f
#define C2 (-1.0f/24.0f)

__device__ __forceinline__ float4 ld4(const float* p) {
    return *reinterpret_cast<const float4*>(p);
}
__device__ __forceinline__ void st4(float* p, float4 v) {
    *reinterpret_cast<float4*>(p) = v;
}
__device__ __forceinline__ float4 f4zero() { return make_float4(0.f,0.f,0.f,0.f); }

__device__ __forceinline__ float frcp(float x) {
    float r; asm("rcp.approx.f32 %0, %1;" : "=f"(r) : "f"(x)); return r;
}
__device__ __forceinline__ float4 frcp4(float4 v) {
    float4 r; r.x = frcp(v.x); r.y = frcp(v.y); r.z = frcp(v.z); r.w = frcp(v.w); return r;
}

// (C1*(a-b) + C2*(c-d)) * s
__device__ __forceinline__ float4 stencil4(float4 a, float4 b, float4 c, float4 d, float s) {
    float4 r;
    r.x = (C1 * (a.x - b.x) + C2 * (c.x - d.x)) * s;
    r.y = (C1 * (a.y - b.y) + C2 * (c.y - d.y)) * s;
    r.z = (C1 * (a.z - b.z) + C2 * (c.z - d.z)) * s;
    r.w = (C1 * (a.w - b.w) + C2 * (c.w - d.w)) * s;
    return r;
}
// update_E x-stencil: lanewise needs x-2..x+1
__device__ __forceinline__ float4 xderiv_E(float4 c, float4 p, float4 n, float s) {
    float4 r;
    r.x = (C1 * (c.x - p.w) + C2 * (c.y - p.z)) * s;
    r.y = (C1 * (c.y - c.x) + C2 * (c.z - p.w)) * s;
    r.z = (C1 * (c.z - c.y) + C2 * (c.w - c.x)) * s;
    r.w = (C1 * (c.w - c.z) + C2 * (n.x - c.y)) * s;
    return r;
}
// update_H x-stencil: lanewise needs x-1..x+2
__device__ __forceinline__ float4 xderiv_H(float4 c, float4 p, float4 n, float s) {
    float4 r;
    r.x = (C1 * (c.y - c.x) + C2 * (c.z - p.w)) * s;
    r.y = (C1 * (c.z - c.y) + C2 * (c.w - c.x)) * s;
    r.z = (C1 * (c.w - c.z) + C2 * (n.x - c.y)) * s;
    r.w = (C1 * (n.x - c.w) + C2 * (n.y - c.z)) * s;
    return r;
}

// ---------------- Kernel 1: update_E (x4 vector, 2 y-rows/thread) ----------------
__global__ void __launch_bounds__(256) upd_E(
    const float* __restrict__ ca, const float* __restrict__ cb,
    const float* __restrict__ Ey, const float* __restrict__ Hx,
    const float* __restrict__ Hz,
    const float* __restrict__ mHxz, const float* __restrict__ mHzx,
    const float* __restrict__ ky, const float* __restrict__ ay,
    const float* __restrict__ by,
    const float* __restrict__ kx, const float* __restrict__ ax,
    const float* __restrict__ bx,
    const float* __restrict__ prdy, const float* __restrict__ prdx,
    float* __restrict__ outEy, float* __restrict__ outmHxz,
    float* __restrict__ outmHzx,
    int NY, int NX)
{
    int x4 = (blockIdx.x * blockDim.x + threadIdx.x) * 4;
    int y0 = (blockIdx.y * blockDim.y + threadIdx.y) * 2;
    int b  = blockIdx.z;
    if (x4 >= NX || y0 >= NY) return;
    int y1 = y0 + 1;                         // NY even -> y1 < NY

    const float rdx = *prdx;
    const float rdy = *prdy;

    size_t plane = (size_t)NY * NX;
    size_t base0 = (size_t)b * plane + (size_t)y0 * NX + x4;
    size_t base1 = base0 + NX;

    // ---- x-derivative of Hz for both rows ----
    float4 c0 = ld4(Hz + base0);
    float4 c1 = ld4(Hz + base1);
    float4 p0 = (x4 >= 4)     ? ld4(Hz + base0 - 4) : f4zero();
    float4 p1 = (x4 >= 4)     ? ld4(Hz + base1 - 4) : f4zero();
    float4 n0 = (x4 + 4 < NX) ? ld4(Hz + base0 + 4) : f4zero();
    float4 n1 = (x4 + 4 < NX) ? ld4(Hz + base1 + 4) : f4zero();
    float4 dHzdx0 = xderiv_E(c0, p0, n0, rdx);
    float4 dHzdx1 = xderiv_E(c1, p1, n1, rdx);

    // ---- y-derivative of Hx: rows y0-2 .. y0+2 (5 loads for 2 rows) ----
    float4 h0 = (y0 >= 2)     ? ld4(Hx + base0 - 2*(size_t)NX) : f4zero();
    float4 h1 = (y0 >= 1)     ? ld4(Hx + base0 - (size_t)NX)   : f4zero();
    float4 h2 = ld4(Hx + base0);
    float4 h3 = ld4(Hx + base1);
    float4 h4 = (y0 + 2 < NY) ? ld4(Hx + base0 + 2*(size_t)NX) : f4zero();
    float4 dHxdz0 = stencil4(h2, h1, h3, h0, rdy);
    float4 dHxdz1 = stencil4(h3, h2, h4, h1, rdy);

    // ---- x coefficients (shared by both rows) ----
    float4 bx4  = ld4(bx + x4);
    float4 ax4  = ld4(ax + x4);
    float4 rkx4 = frcp4(ld4(kx + x4));
    float by0 = by[y0], ay0 = ay[y0], rky0 = frcp(ky[y0]);
    float by1 = by[y1], ay1 = ay[y1], rky1 = frcp(ky[y1]);

    // ---- row y0 ----
    {
        float4 mzx = ld4(mHzx + base0);
        mzx.x = bx4.x * mzx.x + ax4.x * dHzdx0.x;
        mzx.y = bx4.y * mzx.y + ax4.y * dHzdx0.y;
        mzx.z = bx4.z * mzx.z + ax4.z * dHzdx0.z;
        mzx.w = bx4.w * mzx.w + ax4.w * dHzdx0.w;

        float4 mxz = ld4(mHxz + base0);
        mxz.x = by0 * mxz.x + ay0 * dHxdz0.x;
        mxz.y = by0 * mxz.y + ay0 * dHxdz0.y;
        mxz.z = by0 * mxz.z + ay0 * dHxdz0.z;
        mxz.w = by0 * mxz.w + ay0 * dHxdz0.w;

        size_t cidx = (size_t)y0 * NX + x4;
        float4 ca4 = ld4(ca + cidx);
        float4 cb4 = ld4(cb + cidx);
        float4 ey  = ld4(Ey + base0);

        ey.x = ca4.x * ey.x + cb4.x * ((dHzdx0.x * rkx4.x + mzx.x) - (dHxdz0.x * rky0 + mxz.x));
        ey.y = ca4.y * ey.y + cb4.y * ((dHzdx0.y * rkx4.y + mzx.y) - (dHxdz0.y * rky0 + mxz.y));
        ey.z = ca4.z * ey.z + cb4.z * ((dHzdx0.z * rkx4.z + mzx.z) - (dHxdz0.z * rky0 + mxz.z));
        ey.w = ca4.w * ey.w + cb4.w * ((dHzdx0.w * rkx4.w + mzx.w) - (dHxdz0.w * rky0 + mxz.w));

        st4(outEy   + base0, ey);
        st4(outmHzx + base0, mzx);
        st4(outmHxz + base0, mxz);
    }
    // ---- row y1 ----
    {
        float4 mzx = ld4(mHzx + base1);
        mzx.x = bx4.x * mzx.x + ax4.x * dHzdx1.x;
        mzx.y = bx4.y * mzx.y + ax4.y * dHzdx1.y;
        mzx.z = bx4.z * mzx.z + ax4.z * dHzdx1.z;
        mzx.w = bx4.w * mzx.w + ax4.w * dHzdx1.w;

        float4 mxz = ld4(mHxz + base1);
        mxz.x = by1 * mxz.x + ay1 * dHxdz1.x;
        mxz.y = by1 * mxz.y + ay1 * dHxdz1.y;
        mxz.z = by1 * mxz.z + ay1 * dHxdz1.z;
        mxz.w = by1 * mxz.w + ay1 * dHxdz1.w;

        size_t cidx = (size_t)y1 * NX + x4;
        float4 ca4 = ld4(ca + cidx);
        float4 cb4 = ld4(cb + cidx);
        float4 ey  = ld4(Ey + base1);

        ey.x = ca4.x * ey.x + cb4.x * ((dHzdx1.x * rkx4.x + mzx.x) - (dHxdz1.x * rky1 + mxz.x));
        ey.y = ca4.y * ey.y + cb4.y * ((dHzdx1.y * rkx4.y + mzx.y) - (dHxdz1.y * rky1 + mxz.y));
        ey.z = ca4.z * ey.z + cb4.z * ((dHzdx1.z * rkx4.z + mzx.z) - (dHxdz1.z * rky1 + mxz.z));
        ey.w = ca4.w * ey.w + cb4.w * ((dHzdx1.w * rkx4.w + mzx.w) - (dHxdz1.w * rky1 + mxz.w));

        st4(outEy   + base1, ey);
        st4(outmHzx + base1, mzx);
        st4(outmHxz + base1, mxz);
    }
}

// ---------------- Kernel 2: update_H (x4 vector, 2 y-rows/thread) ----------------
__global__ void __launch_bounds__(256) upd_H(
    const float* __restrict__ cq,
    const float* __restrict__ EyNew,
    const float* __restrict__ Hx, const float* __restrict__ Hz,
    const float* __restrict__ mEyx, const float* __restrict__ mEyz,
    const float* __restrict__ kyh, const float* __restrict__ ayh,
    const float* __restrict__ byh,
    const float* __restrict__ kxh, const float* __restrict__ axh,
    const float* __restrict__ bxh,
    const float* __restrict__ prdy, const float* __restrict__ prdx,
    float* __restrict__ outHx, float* __restrict__ outHz,
    float* __restrict__ outmEyx, float* __restrict__ outmEyz,
    int NY, int NX)
{
    int x4 = (blockIdx.x * blockDim.x + threadIdx.x) * 4;
    int y0 = (blockIdx.y * blockDim.y + threadIdx.y) * 2;
    int b  = blockIdx.z;
    if (x4 >= NX || y0 >= NY) return;
    int y1 = y0 + 1;

    const float rdx = *prdx;
    const float rdy = *prdy;

    size_t plane = (size_t)NY * NX;
    size_t base0 = (size_t)b * plane + (size_t)y0 * NX + x4;
    size_t base1 = base0 + NX;

    // ---- EyNew rows: y0-1 .. y0+3 ----
    float4 e0 = (y0 >= 1)     ? ld4(EyNew + base0 - (size_t)NX)   : f4zero();
    float4 e1 = ld4(EyNew + base0);
    float4 e2 = ld4(EyNew + base1);
    float4 e3 = (y0 + 2 < NY) ? ld4(EyNew + base0 + 2*(size_t)NX) : f4zero();
    float4 e4 = (y0 + 3 < NY) ? ld4(EyNew + base0 + 3*(size_t)NX) : f4zero();

    // x-halos for both center rows
    float4 p0 = (x4 >= 4)     ? ld4(EyNew + base0 - 4) : f4zero();
    float4 p1 = (x4 >= 4)     ? ld4(EyNew + base1 - 4) : f4zero();
    float4 n0 = (x4 + 4 < NX) ? ld4(EyNew + base0 + 4) : f4zero();
    float4 n1 = (x4 + 4 < NX) ? ld4(EyNew + base1 + 4) : f4zero();

    float4 dEydx0 = xderiv_H(e1, p0, n0, rdx);
    float4 dEydx1 = xderiv_H(e2, p1, n1, rdx);
    float4 dEydz0 = stencil4(e2, e1, e3, e0, rdy);
    float4 dEydz1 = stencil4(e3, e2, e4, e1, rdy);

    // ---- x coefficients (shared) ----
    float4 bxh4  = ld4(bxh + x4);
    float4 axh4  = ld4(axh + x4);
    float4 rkxh4 = frcp4(ld4(kxh + x4));
    float byh0 = byh[y0], ayh0 = ayh[y0], rkyh0 = frcp(kyh[y0]);
    float byh1 = byh[y1], ayh1 = ayh[y1], rkyh1 = frcp(kyh[y1]);

    // ---- row y0 ----
    {
        float4 mez = ld4(mEyz + base0);
        mez.x = byh0 * mez.x + ayh0 * dEydz0.x;
        mez.y = byh0 * mez.y + ayh0 * dEydz0.y;
        mez.z = byh0 * mez.z + ayh0 * dEydz0.z;
        mez.w = byh0 * mez.w + ayh0 * dEydz0.w;

        float4 mex = ld4(mEyx + base0);
        mex.x = bxh4.x * mex.x + axh4.x * dEydx0.x;
        mex.y = bxh4.y * mex.y + axh4.y * dEydx0.y;
        mex.z = bxh4.z * mex.z + axh4.z * dEydx0.z;
        mex.w = bxh4.w * mex.w + axh4.w * dEydx0.w;

        size_t cidx = (size_t)y0 * NX + x4;
        float4 cq4 = ld4(cq + cidx);

        float4 hx = ld4(Hx + base0);
        hx.x = hx.x - cq4.x * (dEydz0.x * rkyh0 + mez.x);
        hx.y = hx.y - cq4.y * (dEydz0.y * rkyh0 + mez.y);
        hx.z = hx.z - cq4.z * (dEydz0.z * rkyh0 + mez.z);
        hx.w = hx.w - cq4.w * (dEydz0.w * rkyh0 + mez.w);

        float4 hz = ld4(Hz + base0);
        hz.x = hz.x + cq4.x * (dEydx0.x * rkxh4.x + mex.x);
        hz.y = hz.y + cq4.y * (dEydx0.y * rkxh4.y + mex.y);
        hz.z = hz.z + cq4.z * (dEydx0.z * rkxh4.z + mex.z);
        hz.w = hz.w + cq4.w * (dEydx0.w * rkxh4.w + mex.w);

        st4(outHx   + base0, hx);
        st4(outHz   + base0, hz);
        st4(outmEyz + base0, mez);
        st4(outmEyx + base0, mex);
    }
    // ---- row y1 ----
    {
        float4 mez = ld4(mEyz + base1);
        mez.x = byh1 * mez.x + ayh1 * dEydz1.x;
        mez.y = byh1 * mez.y + ayh1 * dEydz1.y;
        mez.z = byh1 * mez.z + ayh1 * dEydz1.z;
        mez.w = byh1 * mez.w + ayh1 * dEydz1.w;

        float4 mex = ld4(mEyx + base1);
        mex.x = bxh4.x * mex.x + axh4.x * dEydx1.x;
        mex.y = bxh4.y * mex.y + axh4.y * dEydx1.y;
        mex.z = bxh4.z * mex.z + axh4.z * dEydx1.z;
        mex.w = bxh4.w * mex.w + axh4.w * dEydx1.w;

        size_t cidx = (size_t)y1 * NX + x4;
        float4 cq4 = ld4(cq + cidx);

        float4 hx = ld4(Hx + base1);
        hx.x = hx.x - cq4.x * (dEydz1.x * rkyh1 + mez.x);
        hx.y = hx.y - cq4.y * (dEydz1.y * rkyh1 + mez.y);
        hx.z = hx.z - cq4.z * (dEydz1.z * rkyh1 + mez.z);
        hx.w = hx.w - cq4.w * (dEydz1.w * rkyh1 + mez.w);

        float4 hz = ld4(Hz + base1);
        hz.x = hz.x + cq4.x * (dEydx1.x * rkxh4.x + mex.x);
        hz.y = hz.y + cq4.y * (dEydx1.y * rkxh4.y + mex.y);
        hz.z = hz.z + cq4.z * (dEydx1.z * rkxh4.z + mex.z);
        hz.w = hz.w + cq4.w * (dEydx1.w * rkxh4.w + mex.w);

        st4(outHx   + base1, hx);
        st4(outHz   + base1, hz);
        st4(outmEyz + base1, mez);
        st4(outmEyx + base1, mex);
    }
}

extern "C" void kernel_launch(void* const* d_in, const int* in_sizes, int n_in,
                              void* d_out, int out_size)
{
    const float* ca    = (const float*)d_in[0];
    const float* cb    = (const float*)d_in[1];
    const float* cq    = (const float*)d_in[2];
    const float* Ey    = (const float*)d_in[3];
    const float* Hx    = (const float*)d_in[4];
    const float* Hz    = (const float*)d_in[5];
    const float* mHxz  = (const float*)d_in[6];
    const float* mHzx  = (const float*)d_in[7];
    const float* mEyx  = (const float*)d_in[8];
    const float* mEyz  = (const float*)d_in[9];
    const float* ky    = (const float*)d_in[10];
    const float* kyh   = (const float*)d_in[11];
    const float* ay    = (const float*)d_in[12];
    const float* ayh   = (const float*)d_in[13];
    const float* by    = (const float*)d_in[14];
    const float* byh   = (const float*)d_in[15];
    const float* kx    = (const float*)d_in[16];
    const float* kxh   = (const float*)d_in[17];
    const float* ax    = (const float*)d_in[18];
    const float* axh   = (const float*)d_in[19];
    const float* bx    = (const float*)d_in[20];
    const float* bxh   = (const float*)d_in[21];
    const float* prdy  = (const float*)d_in[22];
    const float* prdx  = (const float*)d_in[23];

    int NY = in_sizes[10];
    int NX = in_sizes[16];
    int B  = in_sizes[3] / (NY * NX);

    size_t plane = (size_t)NY * NX;
    size_t field = (size_t)B * plane;

    float* out = (float*)d_out;
    float* oEy   = out + 0 * field;
    float* oHx   = out + 1 * field;
    float* oHz   = out + 2 * field;
    float* omHxz = out + 3 * field;
    float* omHzx = out + 4 * field;
    float* omEyx = out + 5 * field;
    float* omEyz = out + 6 * field;

    // each thread: 4 x-elements x 2 y-rows (R10 champion geometry)
    dim3 block(64, 4, 1);
    int nx4 = NX / 4;                       // 512
    int ny2 = (NY + 1) / 2;                 // 1024
    dim3 grid((nx4 + 63) / 64, (ny2 + 3) / 4, B);

    upd_E<<<grid, block>>>(ca, cb, Ey, Hx, Hz, mHxz, mHzx,
                           ky, ay, by, kx, ax, bx, prdy, prdx,
                           oEy, omHxz, omHzx, NY, NX);

    upd_H<<<grid, block>>>(cq, oEy, Hx, Hz, mEyx, mEyz,
                           kyh, ayh, byh, kxh, axh, bxh, prdy, prdx,
                           oHx, oHz, omEyx, omEyz, NY, NX);
}

// round 16
// speedup vs baseline: 1.0250x; 1.0197x over previous
#include <cuda_runtime.h>

#define C1 1.125f
#define C2 (-1.0f/24.0f)

__device__ __forceinline__ float4 ld4(const float* p) {
    return *reinterpret_cast<const float4*>(p);
}
__device__ __forceinline__ void st4(float* p, float4 v) {
    *reinterpret_cast<float4*>(p) = v;
}
__device__ __forceinline__ float4 f4zero() { return make_float4(0.f,0.f,0.f,0.f); }

// elementwise helpers
__device__ __forceinline__ float4 stencil4(float4 a, float4 b, float4 c, float4 d, float s) {
    // (C1*(a-b) + C2*(c-d)) * s
    float4 r;
    r.x = (C1 * (a.x - b.x) + C2 * (c.x - d.x)) * s;
    r.y = (C1 * (a.y - b.y) + C2 * (c.y - d.y)) * s;
    r.z = (C1 * (a.z - b.z) + C2 * (c.z - d.z)) * s;
    r.w = (C1 * (a.w - b.w) + C2 * (c.w - d.w)) * s;
    return r;
}

// x-stencil for update_E: lanewise needs x-2..x+1  (c=center f4, p=prev f4, n=next f4)
__device__ __forceinline__ float4 xderiv_E(float4 c, float4 p, float4 n, float s) {
    float4 r;
    r.x = (C1 * (c.x - p.w) + C2 * (c.y - p.z)) * s;
    r.y = (C1 * (c.y - c.x) + C2 * (c.z - p.w)) * s;
    r.z = (C1 * (c.z - c.y) + C2 * (c.w - c.x)) * s;
    r.w = (C1 * (c.w - c.z) + C2 * (n.x - c.y)) * s;
    return r;
}
// x-stencil for update_H: lanewise needs x-1..x+2
__device__ __forceinline__ float4 xderiv_H(float4 c, float4 p, float4 n, float s) {
    float4 r;
    r.x = (C1 * (c.y - c.x) + C2 * (c.z - p.w)) * s;
    r.y = (C1 * (c.z - c.y) + C2 * (c.w - c.x)) * s;
    r.z = (C1 * (c.w - c.z) + C2 * (n.x - c.y)) * s;
    r.w = (C1 * (n.x - c.w) + C2 * (n.y - c.z)) * s;
    return r;
}

// ---------------- Kernel 1: update_E (x4 vector, 2 y-rows/thread) ----------------
__global__ void __launch_bounds__(256) upd_E(
    const float* __restrict__ ca, const float* __restrict__ cb,
    const float* __restrict__ Ey, const float* __restrict__ Hx,
    const float* __restrict__ Hz,
    const float* __restrict__ mHxz, const float* __restrict__ mHzx,
    const float* __restrict__ ky, const float* __restrict__ ay,
    const float* __restrict__ by,
    const float* __restrict__ kx, const float* __restrict__ ax,
    const float* __restrict__ bx,
    const float* __restrict__ prdy, const float* __restrict__ prdx,
    float* __restrict__ outEy, float* __restrict__ outmHxz,
    float* __restrict__ outmHzx,
    int NY, int NX)
{
    int x4 = (blockIdx.x * blockDim.x + threadIdx.x) * 4;
    int y0 = (blockIdx.y * blockDim.y + threadIdx.y) * 2;
    int b  = blockIdx.z;
    if (x4 >= NX || y0 >= NY) return;
    int y1 = y0 + 1;                         // NY even -> y1 < NY

    const float rdx = *prdx;
    const float rdy = *prdy;

    size_t plane = (size_t)NY * NX;
    size_t base0 = (size_t)b * plane + (size_t)y0 * NX + x4;
    size_t base1 = base0 + NX;

    // ---- x-derivative of Hz for both rows ----
    float4 c0 = ld4(Hz + base0);
    float4 c1 = ld4(Hz + base1);
    float4 p0 = (x4 >= 4)     ? ld4(Hz + base0 - 4) : f4zero();
    float4 p1 = (x4 >= 4)     ? ld4(Hz + base1 - 4) : f4zero();
    float4 n0 = (x4 + 4 < NX) ? ld4(Hz + base0 + 4) : f4zero();
    float4 n1 = (x4 + 4 < NX) ? ld4(Hz + base1 + 4) : f4zero();
    float4 dHzdx0 = xderiv_E(c0, p0, n0, rdx);
    float4 dHzdx1 = xderiv_E(c1, p1, n1, rdx);

    // ---- y-derivative of Hx: rows y0-2 .. y0+2 (5 loads for 2 rows) ----
    float4 h0 = (y0 >= 2)     ? ld4(Hx + base0 - 2*(size_t)NX) : f4zero();
    float4 h1 = (y0 >= 1)     ? ld4(Hx + base0 - (size_t)NX)   : f4zero();
    float4 h2 = ld4(Hx + base0);
    float4 h3 = ld4(Hx + base1);
    float4 h4 = (y0 + 2 < NY) ? ld4(Hx + base0 + 2*(size_t)NX) : f4zero();
    float4 dHxdz0 = stencil4(h2, h1, h3, h0, rdy);   // row y0: C1*(h[y]-h[y-1])+C2*(h[y+1]-h[y-2])
    float4 dHxdz1 = stencil4(h3, h2, h4, h1, rdy);   // row y1

    // ---- x coefficients (shared by both rows) ----
    float4 bx4 = ld4(bx + x4);
    float4 ax4 = ld4(ax + x4);
    float4 kx4 = ld4(kx + x4);
    // y coefficients per row
    float by0 = by[y0], ay0 = ay[y0], rky0 = 1.0f / ky[y0];
    float by1 = by[y1], ay1 = ay[y1], rky1 = 1.0f / ky[y1];

    // ---- row y0 ----
    {
        float4 mzx = ld4(mHzx + base0);
        mzx.x = bx4.x * mzx.x + ax4.x * dHzdx0.x;
        mzx.y = bx4.y * mzx.y + ax4.y * dHzdx0.y;
        mzx.z = bx4.z * mzx.z + ax4.z * dHzdx0.z;
        mzx.w = bx4.w * mzx.w + ax4.w * dHzdx0.w;

        float4 mxz = ld4(mHxz + base0);
        mxz.x = by0 * mxz.x + ay0 * dHxdz0.x;
        mxz.y = by0 * mxz.y + ay0 * dHxdz0.y;
        mxz.z = by0 * mxz.z + ay0 * dHxdz0.z;
        mxz.w = by0 * mxz.w + ay0 * dHxdz0.w;

        size_t cidx = (size_t)y0 * NX + x4;
        float4 ca4 = ld4(ca + cidx);
        float4 cb4 = ld4(cb + cidx);
        float4 ey  = ld4(Ey + base0);

        ey.x = ca4.x * ey.x + cb4.x * ((dHzdx0.x / kx4.x + mzx.x) - (dHxdz0.x * rky0 + mxz.x));
        ey.y = ca4.y * ey.y + cb4.y * ((dHzdx0.y / kx4.y + mzx.y) - (dHxdz0.y * rky0 + mxz.y));
        ey.z = ca4.z * ey.z + cb4.z * ((dHzdx0.z / kx4.z + mzx.z) - (dHxdz0.z * rky0 + mxz.z));
        ey.w = ca4.w * ey.w + cb4.w * ((dHzdx0.w / kx4.w + mzx.w) - (dHxdz0.w * rky0 + mxz.w));

        st4(outEy   + base0, ey);
        st4(outmHzx + base0, mzx);
        st4(outmHxz + base0, mxz);
    }
    // ---- row y1 ----
    {
        float4 mzx = ld4(mHzx + base1);
        mzx.x = bx4.x * mzx.x + ax4.x * dHzdx1.x;
        mzx.y = bx4.y * mzx.y + ax4.y * dHzdx1.y;
        mzx.z = bx4.z * mzx.z + ax4.z * dHzdx1.z;
        mzx.w = bx4.w * mzx.w + ax4.w * dHzdx1.w;

        float4 mxz = ld4(mHxz + base1);
        mxz.x = by1 * mxz.x + ay1 * dHxdz1.x;
        mxz.y = by1 * mxz.y + ay1 * dHxdz1.y;
        mxz.z = by1 * mxz.z + ay1 * dHxdz1.z;
        mxz.w = by1 * mxz.w + ay1 * dHxdz1.w;

        size_t cidx = (size_t)y1 * NX + x4;
        float4 ca4 = ld4(ca + cidx);
        float4 cb4 = ld4(cb + cidx);
        float4 ey  = ld4(Ey + base1);

        ey.x = ca4.x * ey.x + cb4.x * ((dHzdx1.x / kx4.x + mzx.x) - (dHxdz1.x * rky1 + mxz.x));
        ey.y = ca4.y * ey.y + cb4.y * ((dHzdx1.y / kx4.y + mzx.y) - (dHxdz1.y * rky1 + mxz.y));
        ey.z = ca4.z * ey.z + cb4.z * ((dHzdx1.z / kx4.z + mzx.z) - (dHxdz1.z * rky1 + mxz.z));
        ey.w = ca4.w * ey.w + cb4.w * ((dHzdx1.w / kx4.w + mzx.w) - (dHxdz1.w * rky1 + mxz.w));

        st4(outEy   + base1, ey);
        st4(outmHzx + base1, mzx);
        st4(outmHxz + base1, mxz);
    }
}

// ---------------- Kernel 2: update_H (x4 vector, 2 y-rows/thread) ----------------
__global__ void __launch_bounds__(256) upd_H(
    const float* __restrict__ cq,
    const float* __restrict__ EyNew,
    const float* __restrict__ Hx, const float* __restrict__ Hz,
    const float* __restrict__ mEyx, const float* __restrict__ mEyz,
    const float* __restrict__ kyh, const float* __restrict__ ayh,
    const float* __restrict__ byh,
    const float* __restrict__ kxh, const float* __restrict__ axh,
    const float* __restrict__ bxh,
    const float* __restrict__ prdy, const float* __restrict__ prdx,
    float* __restrict__ outHx, float* __restrict__ outHz,
    float* __restrict__ outmEyx, float* __restrict__ outmEyz,
    int NY, int NX)
{
    int x4 = (blockIdx.x * blockDim.x + threadIdx.x) * 4;
    int y0 = (blockIdx.y * blockDim.y + threadIdx.y) * 2;
    int b  = blockIdx.z;
    if (x4 >= NX || y0 >= NY) return;
    int y1 = y0 + 1;

    const float rdx = *prdx;
    const float rdy = *prdy;

    size_t plane = (size_t)NY * NX;
    size_t base0 = (size_t)b * plane + (size_t)y0 * NX + x4;
    size_t base1 = base0 + NX;

    // ---- EyNew rows: y0-1 .. y0+3 (centers e1,e2 shared with x-deriv) ----
    float4 e0 = (y0 >= 1)     ? ld4(EyNew + base0 - (size_t)NX)   : f4zero();
    float4 e1 = ld4(EyNew + base0);
    float4 e2 = ld4(EyNew + base1);
    float4 e3 = (y0 + 2 < NY) ? ld4(EyNew + base0 + 2*(size_t)NX) : f4zero();
    float4 e4 = (y0 + 3 < NY) ? ld4(EyNew + base0 + 3*(size_t)NX) : f4zero();

    // x-halos for both center rows
    float4 p0 = (x4 >= 4)     ? ld4(EyNew + base0 - 4) : f4zero();
    float4 p1 = (x4 >= 4)     ? ld4(EyNew + base1 - 4) : f4zero();
    float4 n0 = (x4 + 4 < NX) ? ld4(EyNew + base0 + 4) : f4zero();
    float4 n1 = (x4 + 4 < NX) ? ld4(EyNew + base1 + 4) : f4zero();

    float4 dEydx0 = xderiv_H(e1, p0, n0, rdx);
    float4 dEydx1 = xderiv_H(e2, p1, n1, rdx);
    // half-grid y-deriv: row y uses y+1, y, y+2, y-1
    float4 dEydz0 = stencil4(e2, e1, e3, e0, rdy);
    float4 dEydz1 = stencil4(e3, e2, e4, e1, rdy);

    // ---- x coefficients (shared) ----
    float4 bxh4 = ld4(bxh + x4);
    float4 axh4 = ld4(axh + x4);
    float4 kxh4 = ld4(kxh + x4);
    float byh0 = byh[y0], ayh0 = ayh[y0], rkyh0 = 1.0f / kyh[y0];
    float byh1 = byh[y1], ayh1 = ayh[y1], rkyh1 = 1.0f / kyh[y1];

    // ---- row y0 ----
    {
        float4 mez = ld4(mEyz + base0);
        mez.x = byh0 * mez.x + ayh0 * dEydz0.x;
        mez.y = byh0 * mez.y + ayh0 * dEydz0.y;
        mez.z = byh0 * mez.z + ayh0 * dEydz0.z;
        mez.w = byh0 * mez.w + ayh0 * dEydz0.w;

        float4 mex = ld4(mEyx + base0);
        mex.x = bxh4.x * mex.x + axh4.x * dEydx0.x;
        mex.y = bxh4.y * mex.y + axh4.y * dEydx0.y;
        mex.z = bxh4.z * mex.z + axh4.z * dEydx0.z;
        mex.w = bxh4.w * mex.w + axh4.w * dEydx0.w;

        size_t cidx = (size_t)y0 * NX + x4;
        float4 cq4 = ld4(cq + cidx);

        float4 hx = ld4(Hx + base0);
        hx.x = hx.x - cq4.x * (dEydz0.x * rkyh0 + mez.x);
        hx.y = hx.y - cq4.y * (dEydz0.y * rkyh0 + mez.y);
        hx.z = hx.z - cq4.z * (dEydz0.z * rkyh0 + mez.z);
        hx.w = hx.w - cq4.w * (dEydz0.w * rkyh0 + mez.w);

        float4 hz = ld4(Hz + base0);
        hz.x = hz.x + cq4.x * (dEydx0.x / kxh4.x + mex.x);
        hz.y = hz.y + cq4.y * (dEydx0.y / kxh4.y + mex.y);
        hz.z = hz.z + cq4.z * (dEydx0.z / kxh4.z + mex.z);
        hz.w = hz.w + cq4.w * (dEydx0.w / kxh4.w + mex.w);

        st4(outHx   + base0, hx);
        st4(outHz   + base0, hz);
        st4(outmEyz + base0, mez);
        st4(outmEyx + base0, mex);
    }
    // ---- row y1 ----
    {
        float4 mez = ld4(mEyz + base1);
        mez.x = byh1 * mez.x + ayh1 * dEydz1.x;
        mez.y = byh1 * mez.y + ayh1 * dEydz1.y;
        mez.z = byh1 * mez.z + ayh1 * dEydz1.z;
        mez.w = byh1 * mez.w + ayh1 * dEydz1.w;

        float4 mex = ld4(mEyx + base1);
        mex.x = bxh4.x * mex.x + axh4.x * dEydx1.x;
        mex.y = bxh4.y * mex.y + axh4.y * dEydx1.y;
        mex.z = bxh4.z * mex.z + axh4.z * dEydx1.z;
        mex.w = bxh4.w * mex.w + axh4.w * dEydx1.w;

        size_t cidx = (size_t)y1 * NX + x4;
        float4 cq4 = ld4(cq + cidx);

        float4 hx = ld4(Hx + base1);
        hx.x = hx.x - cq4.x * (dEydz1.x * rkyh1 + mez.x);
        hx.y = hx.y - cq4.y * (dEydz1.y * rkyh1 + mez.y);
        hx.z = hx.z - cq4.z * (dEydz1.z * rkyh1 + mez.z);
        hx.w = hx.w - cq4.w * (dEydz1.w * rkyh1 + mez.w);

        float4 hz = ld4(Hz + base1);
        hz.x = hz.x + cq4.x * (dEydx1.x / kxh4.x + mex.x);
        hz.y = hz.y + cq4.y * (dEydx1.y / kxh4.y + mex.y);
        hz.z = hz.z + cq4.z * (dEydx1.z / kxh4.z + mex.z);
        hz.w = hz.w + cq4.w * (dEydx1.w / kxh4.w + mex.w);

        st4(outHx   + base1, hx);
        st4(outHz   + base1, hz);
        st4(outmEyz + base1, mez);
        st4(outmEyx + base1, mex);
    }
}

extern "C" void kernel_launch(void* const* d_in, const int* in_sizes, int n_in,
                              void* d_out, int out_size)
{
    const float* ca    = (const float*)d_in[0];
    const float* cb    = (const float*)d_in[1];
    const float* cq    = (const float*)d_in[2];
    const float* Ey    = (const float*)d_in[3];
    const float* Hx    = (const float*)d_in[4];
    const float* Hz    = (const float*)d_in[5];
    const float* mHxz  = (const float*)d_in[6];
    const float* mHzx  = (const float*)d_in[7];
    const float* mEyx  = (const float*)d_in[8];
    const float* mEyz  = (const float*)d_in[9];
    const float* ky    = (const float*)d_in[10];
    const float* kyh   = (const float*)d_in[11];
    const float* ay    = (const float*)d_in[12];
    const float* ayh   = (const float*)d_in[13];
    const float* by    = (const float*)d_in[14];
    const float* byh   = (const float*)d_in[15];
    const float* kx    = (const float*)d_in[16];
    const float* kxh   = (const float*)d_in[17];
    const float* ax    = (const float*)d_in[18];
    const float* axh   = (const float*)d_in[19];
    const float* bx    = (const float*)d_in[20];
    const float* bxh   = (const float*)d_in[21];
    const float* prdy  = (const float*)d_in[22];
    const float* prdx  = (const float*)d_in[23];

    int NY = in_sizes[10];
    int NX = in_sizes[16];
    int B  = in_sizes[3] / (NY * NX);

    size_t plane = (size_t)NY * NX;
    size_t field = (size_t)B * plane;

    float* out = (float*)d_out;
    float* oEy   = out + 0 * field;
    float* oHx   = out + 1 * field;
    float* oHz   = out + 2 * field;
    float* omHxz = out + 3 * field;
    float* omHzx = out + 4 * field;
    float* omEyx = out + 5 * field;
    float* omEyz = out + 6 * field;

    // each thread: 4 x-elements x 2 y-rows (champion geometry, R10)
    dim3 block(64, 4, 1);
    int nx4 = NX / 4;                       // 512
    int ny2 = (NY + 1) / 2;                 // 1024
    dim3 grid((nx4 + 63) / 64, (ny2 + 3) / 4, B);

    upd_E<<<grid, block>>>(ca, cb, Ey, Hx, Hz, mHxz, mHzx,
                           ky, ay, by, kx, ax, bx, prdy, prdx,
                           oEy, omHxz, omHzx, NY, NX);

    upd_H<<<grid, block>>>(cq, oEy, Hx, Hz, mEyx, mEyz,
                           kyh, ayh, byh, kxh, axh, bxh, prdy, prdx,
                           oHx, oHz, omEyx, omEyz, NY, NX);
}

// round 17
// speedup vs baseline: 1.0865x; 1.0600x over previous
#include <cuda_runtime.h>

#define C1 1.125f
#define C2 (-1.0f/24.0f)

__device__ __forceinline__ float4 ld4(const float* p) {
    return *reinterpret_cast<const float4*>(p);
}
__device__ __forceinline__ void st4(float* p, float4 v) {
    *reinterpret_cast<float4*>(p) = v;
}
__device__ __forceinline__ float4 f4zero() { return make_float4(0.f,0.f,0.f,0.f); }

// (C1*(a-b) + C2*(c-d)) * s
__device__ __forceinline__ float4 stencil4(float4 a, float4 b, float4 c, float4 d, float s) {
    float4 r;
    r.x = (C1 * (a.x - b.x) + C2 * (c.x - d.x)) * s;
    r.y = (C1 * (a.y - b.y) + C2 * (c.y - d.y)) * s;
    r.z = (C1 * (a.z - b.z) + C2 * (c.z - d.z)) * s;
    r.w = (C1 * (a.w - b.w) + C2 * (c.w - d.w)) * s;
    return r;
}
// update_E x-stencil: lanewise needs x-2..x+1
__device__ __forceinline__ float4 xderiv_E(float4 c, float4 p, float4 n, float s) {
    float4 r;
    r.x = (C1 * (c.x - p.w) + C2 * (c.y - p.z)) * s;
    r.y = (C1 * (c.y - c.x) + C2 * (c.z - p.w)) * s;
    r.z = (C1 * (c.z - c.y) + C2 * (c.w - c.x)) * s;
    r.w = (C1 * (c.w - c.z) + C2 * (n.x - c.y)) * s;
    return r;
}
// update_H x-stencil: lanewise needs x-1..x+2
__device__ __forceinline__ float4 xderiv_H(float4 c, float4 p, float4 n, float s) {
    float4 r;
    r.x = (C1 * (c.y - c.x) + C2 * (c.z - p.w)) * s;
    r.y = (C1 * (c.z - c.y) + C2 * (c.w - c.x)) * s;
    r.z = (C1 * (c.w - c.z) + C2 * (n.x - c.y)) * s;
    r.w = (C1 * (n.x - c.w) + C2 * (n.y - c.z)) * s;
    return r;
}

// grid axes: x = batch (fastest-varying), y = x-tile, z = y-tile
// ---------------- Kernel 1: update_E (x4 vector, 2 y-rows/thread) ----------------
__global__ void __launch_bounds__(256) upd_E(
    const float* __restrict__ ca, const float* __restrict__ cb,
    const float* __restrict__ Ey, const float* __restrict__ Hx,
    const float* __restrict__ Hz,
    const float* __restrict__ mHxz, const float* __restrict__ mHzx,
    const float* __restrict__ ky, const float* __restrict__ ay,
    const float* __restrict__ by,
    const float* __restrict__ kx, const float* __restrict__ ax,
    const float* __restrict__ bx,
    const float* __restrict__ prdy, const float* __restrict__ prdx,
    float* __restrict__ outEy, float* __restrict__ outmHxz,
    float* __restrict__ outmHzx,
    int NY, int NX)
{
    int b  = blockIdx.x;                                   // batch fastest
    int x4 = (blockIdx.y * blockDim.x + threadIdx.x) * 4;
    int y0 = (blockIdx.z * blockDim.y + threadIdx.y) * 2;
    if (x4 >= NX || y0 >= NY) return;
    int y1 = y0 + 1;                         // NY even -> y1 < NY

    const float rdx = *prdx;
    const float rdy = *prdy;

    size_t plane = (size_t)NY * NX;
    size_t base0 = (size_t)b * plane + (size_t)y0 * NX + x4;
    size_t base1 = base0 + NX;

    // ---- x-derivative of Hz for both rows ----
    float4 c0 = ld4(Hz + base0);
    float4 c1 = ld4(Hz + base1);
    float4 p0 = (x4 >= 4)     ? ld4(Hz + base0 - 4) : f4zero();
    float4 p1 = (x4 >= 4)     ? ld4(Hz + base1 - 4) : f4zero();
    float4 n0 = (x4 + 4 < NX) ? ld4(Hz + base0 + 4) : f4zero();
    float4 n1 = (x4 + 4 < NX) ? ld4(Hz + base1 + 4) : f4zero();
    float4 dHzdx0 = xderiv_E(c0, p0, n0, rdx);
    float4 dHzdx1 = xderiv_E(c1, p1, n1, rdx);

    // ---- y-derivative of Hx: rows y0-2 .. y0+2 (5 loads for 2 rows) ----
    float4 h0 = (y0 >= 2)     ? ld4(Hx + base0 - 2*(size_t)NX) : f4zero();
    float4 h1 = (y0 >= 1)     ? ld4(Hx + base0 - (size_t)NX)   : f4zero();
    float4 h2 = ld4(Hx + base0);
    float4 h3 = ld4(Hx + base1);
    float4 h4 = (y0 + 2 < NY) ? ld4(Hx + base0 + 2*(size_t)NX) : f4zero();
    float4 dHxdz0 = stencil4(h2, h1, h3, h0, rdy);
    float4 dHxdz1 = stencil4(h3, h2, h4, h1, rdy);

    // ---- x coefficients (shared by both rows) ----
    float4 bx4 = ld4(bx + x4);
    float4 ax4 = ld4(ax + x4);
    float4 kx4 = ld4(kx + x4);
    float by0 = by[y0], ay0 = ay[y0], rky0 = 1.0f / ky[y0];
    float by1 = by[y1], ay1 = ay[y1], rky1 = 1.0f / ky[y1];

    // ---- row y0 ----
    {
        float4 mzx = ld4(mHzx + base0);
        mzx.x = bx4.x * mzx.x + ax4.x * dHzdx0.x;
        mzx.y = bx4.y * mzx.y + ax4.y * dHzdx0.y;
        mzx.z = bx4.z * mzx.z + ax4.z * dHzdx0.z;
        mzx.w = bx4.w * mzx.w + ax4.w * dHzdx0.w;

        float4 mxz = ld4(mHxz + base0);
        mxz.x = by0 * mxz.x + ay0 * dHxdz0.x;
        mxz.y = by0 * mxz.y + ay0 * dHxdz0.y;
        mxz.z = by0 * mxz.z + ay0 * dHxdz0.z;
        mxz.w = by0 * mxz.w + ay0 * dHxdz0.w;

        size_t cidx = (size_t)y0 * NX + x4;
        float4 ca4 = ld4(ca + cidx);
        float4 cb4 = ld4(cb + cidx);
        float4 ey  = ld4(Ey + base0);

        ey.x = ca4.x * ey.x + cb4.x * ((dHzdx0.x / kx4.x + mzx.x) - (dHxdz0.x * rky0 + mxz.x));
        ey.y = ca4.y * ey.y + cb4.y * ((dHzdx0.y / kx4.y + mzx.y) - (dHxdz0.y * rky0 + mxz.y));
        ey.z = ca4.z * ey.z + cb4.z * ((dHzdx0.z / kx4.z + mzx.z) - (dHxdz0.z * rky0 + mxz.z));
        ey.w = ca4.w * ey.w + cb4.w * ((dHzdx0.w / kx4.w + mzx.w) - (dHxdz0.w * rky0 + mxz.w));

        st4(outEy   + base0, ey);
        st4(outmHzx + base0, mzx);
        st4(outmHxz + base0, mxz);
    }
    // ---- row y1 ----
    {
        float4 mzx = ld4(mHzx + base1);
        mzx.x = bx4.x * mzx.x + ax4.x * dHzdx1.x;
        mzx.y = bx4.y * mzx.y + ax4.y * dHzdx1.y;
        mzx.z = bx4.z * mzx.z + ax4.z * dHzdx1.z;
        mzx.w = bx4.w * mzx.w + ax4.w * dHzdx1.w;

        float4 mxz = ld4(mHxz + base1);
        mxz.x = by1 * mxz.x + ay1 * dHxdz1.x;
        mxz.y = by1 * mxz.y + ay1 * dHxdz1.y;
        mxz.z = by1 * mxz.z + ay1 * dHxdz1.z;
        mxz.w = by1 * mxz.w + ay1 * dHxdz1.w;

        size_t cidx = (size_t)y1 * NX + x4;
        float4 ca4 = ld4(ca + cidx);
        float4 cb4 = ld4(cb + cidx);
        float4 ey  = ld4(Ey + base1);

        ey.x = ca4.x * ey.x + cb4.x * ((dHzdx1.x / kx4.x + mzx.x) - (dHxdz1.x * rky1 + mxz.x));
        ey.y = ca4.y * ey.y + cb4.y * ((dHzdx1.y / kx4.y + mzx.y) - (dHxdz1.y * rky1 + mxz.y));
        ey.z = ca4.z * ey.z + cb4.z * ((dHzdx1.z / kx4.z + mzx.z) - (dHxdz1.z * rky1 + mxz.z));
        ey.w = ca4.w * ey.w + cb4.w * ((dHzdx1.w / kx4.w + mzx.w) - (dHxdz1.w * rky1 + mxz.w));

        st4(outEy   + base1, ey);
        st4(outmHzx + base1, mzx);
        st4(outmHxz + base1, mxz);
    }
}

// ---------------- Kernel 2: update_H (x4 vector, 2 y-rows/thread) ----------------
__global__ void __launch_bounds__(256) upd_H(
    const float* __restrict__ cq,
    const float* __restrict__ EyNew,
    const float* __restrict__ Hx, const float* __restrict__ Hz,
    const float* __restrict__ mEyx, const float* __restrict__ mEyz,
    const float* __restrict__ kyh, const float* __restrict__ ayh,
    const float* __restrict__ byh,
    const float* __restrict__ kxh, const float* __restrict__ axh,
    const float* __restrict__ bxh,
    const float* __restrict__ prdy, const float* __restrict__ prdx,
    float* __restrict__ outHx, float* __restrict__ outHz,
    float* __restrict__ outmEyx, float* __restrict__ outmEyz,
    int NY, int NX)
{
    int b  = blockIdx.x;                                   // batch fastest
    int x4 = (blockIdx.y * blockDim.x + threadIdx.x) * 4;
    int y0 = (blockIdx.z * blockDim.y + threadIdx.y) * 2;
    if (x4 >= NX || y0 >= NY) return;
    int y1 = y0 + 1;

    const float rdx = *prdx;
    const float rdy = *prdy;

    size_t plane = (size_t)NY * NX;
    size_t base0 = (size_t)b * plane + (size_t)y0 * NX + x4;
    size_t base1 = base0 + NX;

    // ---- EyNew rows: y0-1 .. y0+3 ----
    float4 e0 = (y0 >= 1)     ? ld4(EyNew + base0 - (size_t)NX)   : f4zero();
    float4 e1 = ld4(EyNew + base0);
    float4 e2 = ld4(EyNew + base1);
    float4 e3 = (y0 + 2 < NY) ? ld4(EyNew + base0 + 2*(size_t)NX) : f4zero();
    float4 e4 = (y0 + 3 < NY) ? ld4(EyNew + base0 + 3*(size_t)NX) : f4zero();

    // x-halos for both center rows
    float4 p0 = (x4 >= 4)     ? ld4(EyNew + base0 - 4) : f4zero();
    float4 p1 = (x4 >= 4)     ? ld4(EyNew + base1 - 4) : f4zero();
    float4 n0 = (x4 + 4 < NX) ? ld4(EyNew + base0 + 4) : f4zero();
    float4 n1 = (x4 + 4 < NX) ? ld4(EyNew + base1 + 4) : f4zero();

    float4 dEydx0 = xderiv_H(e1, p0, n0, rdx);
    float4 dEydx1 = xderiv_H(e2, p1, n1, rdx);
    float4 dEydz0 = stencil4(e2, e1, e3, e0, rdy);
    float4 dEydz1 = stencil4(e3, e2, e4, e1, rdy);

    // ---- x coefficients (shared) ----
    float4 bxh4 = ld4(bxh + x4);
    float4 axh4 = ld4(axh + x4);
    float4 kxh4 = ld4(kxh + x4);
    float byh0 = byh[y0], ayh0 = ayh[y0], rkyh0 = 1.0f / kyh[y0];
    float byh1 = byh[y1], ayh1 = ayh[y1], rkyh1 = 1.0f / kyh[y1];

    // ---- row y0 ----
    {
        float4 mez = ld4(mEyz + base0);
        mez.x = byh0 * mez.x + ayh0 * dEydz0.x;
        mez.y = byh0 * mez.y + ayh0 * dEydz0.y;
        mez.z = byh0 * mez.z + ayh0 * dEydz0.z;
        mez.w = byh0 * mez.w + ayh0 * dEydz0.w;

        float4 mex = ld4(mEyx + base0);
        mex.x = bxh4.x * mex.x + axh4.x * dEydx0.x;
        mex.y = bxh4.y * mex.y + axh4.y * dEydx0.y;
        mex.z = bxh4.z * mex.z + axh4.z * dEydx0.z;
        mex.w = bxh4.w * mex.w + axh4.w * dEydx0.w;

        size_t cidx = (size_t)y0 * NX + x4;
        float4 cq4 = ld4(cq + cidx);

        float4 hx = ld4(Hx + base0);
        hx.x = hx.x - cq4.x * (dEydz0.x * rkyh0 + mez.x);
        hx.y = hx.y - cq4.y * (dEydz0.y * rkyh0 + mez.y);
        hx.z = hx.z - cq4.z * (dEydz0.z * rkyh0 + mez.z);
        hx.w = hx.w - cq4.w * (dEydz0.w * rkyh0 + mez.w);

        float4 hz = ld4(Hz + base0);
        hz.x = hz.x + cq4.x * (dEydx0.x / kxh4.x + mex.x);
        hz.y = hz.y + cq4.y * (dEydx0.y / kxh4.y + mex.y);
        hz.z = hz.z + cq4.z * (dEydx0.z / kxh4.z + mex.z);
        hz.w = hz.w + cq4.w * (dEydx0.w / kxh4.w + mex.w);

        st4(outHx   + base0, hx);
        st4(outHz   + base0, hz);
        st4(outmEyz + base0, mez);
        st4(outmEyx + base0, mex);
    }
    // ---- row y1 ----
    {
        float4 mez = ld4(mEyz + base1);
        mez.x = byh1 * mez.x + ayh1 * dEydz1.x;
        mez.y = byh1 * mez.y + ayh1 * dEydz1.y;
        mez.z = byh1 * mez.z + ayh1 * dEydz1.z;
        mez.w = byh1 * mez.w + ayh1 * dEydz1.w;

        float4 mex = ld4(mEyx + base1);
        mex.x = bxh4.x * mex.x + axh4.x * dEydx1.x;
        mex.y = bxh4.y * mex.y + axh4.y * dEydx1.y;
        mex.z = bxh4.z * mex.z + axh4.z * dEydx1.z;
        mex.w = bxh4.w * mex.w + axh4.w * dEydx1.w;

        size_t cidx = (size_t)y1 * NX + x4;
        float4 cq4 = ld4(cq + cidx);

        float4 hx = ld4(Hx + base1);
        hx.x = hx.x - cq4.x * (dEydz1.x * rkyh1 + mez.x);
        hx.y = hx.y - cq4.y * (dEydz1.y * rkyh1 + mez.y);
        hx.z = hx.z - cq4.z * (dEydz1.z * rkyh1 + mez.z);
        hx.w = hx.w - cq4.w * (dEydz1.w * rkyh1 + mez.w);

        float4 hz = ld4(Hz + base1);
        hz.x = hz.x + cq4.x * (dEydx1.x / kxh4.x + mex.x);
        hz.y = hz.y + cq4.y * (dEydx1.y / kxh4.y + mex.y);
        hz.z = hz.z + cq4.z * (dEydx1.z / kxh4.z + mex.z);
        hz.w = hz.w + cq4.w * (dEydx1.w / kxh4.w + mex.w);

        st4(outHx   + base1, hx);
        st4(outHz   + base1, hz);
        st4(outmEyz + base1, mez);
        st4(outmEyx + base1, mex);
    }
}

extern "C" void kernel_launch(void* const* d_in, const int* in_sizes, int n_in,
                              void* d_out, int out_size)
{
    const float* ca    = (const float*)d_in[0];
    const float* cb    = (const float*)d_in[1];
    const float* cq    = (const float*)d_in[2];
    const float* Ey    = (const float*)d_in[3];
    const float* Hx    = (const float*)d_in[4];
    const float* Hz    = (const float*)d_in[5];
    const float* mHxz  = (const float*)d_in[6];
    const float* mHzx  = (const float*)d_in[7];
    const float* mEyx  = (const float*)d_in[8];
    const float* mEyz  = (const float*)d_in[9];
    const float* ky    = (const float*)d_in[10];
    const float* kyh   = (const float*)d_in[11];
    const float* ay    = (const float*)d_in[12];
    const float* ayh   = (const float*)d_in[13];
    const float* by    = (const float*)d_in[14];
    const float* byh   = (const float*)d_in[15];
    const float* kx    = (const float*)d_in[16];
    const float* kxh   = (const float*)d_in[17];
    const float* ax    = (const float*)d_in[18];
    const float* axh   = (const float*)d_in[19];
    const float* bx    = (const float*)d_in[20];
    const float* bxh   = (const float*)d_in[21];
    const float* prdy  = (const float*)d_in[22];
    const float* prdx  = (const float*)d_in[23];

    int NY = in_sizes[10];
    int NX = in_sizes[16];
    int B  = in_sizes[3] / (NY * NX);

    size_t plane = (size_t)NY * NX;
    size_t field = (size_t)B * plane;

    float* out = (float*)d_out;
    float* oEy   = out + 0 * field;
    float* oHx   = out + 1 * field;
    float* oHz   = out + 2 * field;
    float* omHxz = out + 3 * field;
    float* omHzx = out + 4 * field;
    float* omEyx = out + 5 * field;
    float* omEyz = out + 6 * field;

    // champion geometry (R10): 4 x-elements x 2 y-rows per thread.
    // grid axes reordered: x = batch (fastest), y = x-tile, z = y-tile.
    dim3 block(64, 4, 1);
    int nx4 = NX / 4;                       // 512
    int ny2 = (NY + 1) / 2;                 // 1024
    dim3 grid(B, (nx4 + 63) / 64, (ny2 + 3) / 4);

    upd_E<<<grid, block>>>(ca, cb, Ey, Hx, Hz, mHxz, mHzx,
                           ky, ay, by, kx, ax, bx, prdy, prdx,
                           oEy, omHxz, omHzx, NY, NX);

    upd_H<<<grid, block>>>(cq, oEy, Hx, Hz, mEyx, mEyz,
                           kyh, ayh, byh, kxh, axh, bxh, prdy, prdx,
                           oHx, oHz, omEyx, omEyz, NY, NX);
}